// round 6
// baseline (speedup 1.0000x reference)
#include <cuda_runtime.h>
#include <cuda_bf16.h>
#include <cstdint>
#include <math.h>

#define B_    2
#define S_    2048
#define H_    16
#define NROWS 4096          // B_*S_

// ---------------- scratch (device globals: no allocs allowed) ----------------
__device__ float g_Q[NROWS * 4096];                  // (b,s,h,256) nope|rope(pe)  fp32
__device__ float g_KV[NROWS * 768];                  // x @ wkv_a (padded 640->768)
__device__ float g_KPE[NROWS * 128];                 // roped k_pe
__device__ float g_KVB[NROWS * 2048];                // (b,s,kvh,256) k_nope|v fp32
__device__ float g_COS[S_ * 64];
__device__ float g_SIN[S_ * 64];
// bf16 split-cat buffers (GEMMs): A=[hi,lo,hi], B(transposed)=[hi,hi,lo]
__device__ __nv_bfloat16 g_Xc[NROWS * 6144];
__device__ __nv_bfloat16 g_KVCc[NROWS * 1536];
__device__ __nv_bfloat16 g_ATTNc[NROWS * 6144];
__device__ __nv_bfloat16 g_WqT[4096 * 6144];
__device__ __nv_bfloat16 g_WkvaT[768 * 6144];
__device__ __nv_bfloat16 g_WkvbT[2048 * 1536];
__device__ __nv_bfloat16 g_WoT[2048 * 6144];
// bf16 hi/lo planes for flash attention
__device__ __nv_bfloat16 g_Qh[NROWS * 4096];         // (b,s,h,256)
__device__ __nv_bfloat16 g_Ql[NROWS * 4096];
__device__ __nv_bfloat16 g_Kh[NROWS * 2048];         // (b,s,kvh,256) nope|pe
__device__ __nv_bfloat16 g_Kl[NROWS * 2048];
__device__ __nv_bfloat16 g_Vh[NROWS * 1024];         // (b,s,kvh,128)
__device__ __nv_bfloat16 g_Vl[NROWS * 1024];

// ================= helpers =================
__device__ __forceinline__ uint32_t smem_u32(const void* p) {
    uint32_t a;
    asm("{ .reg .u64 t; cvta.to.shared.u64 t, %1; cvt.u32.u64 %0, t; }" : "=r"(a) : "l"(p));
    return a;
}
__device__ __forceinline__ void cp_async16(uint32_t saddr, const void* gaddr) {
    asm volatile("cp.async.cg.shared.global [%0], [%1], 16;" :: "r"(saddr), "l"(gaddr));
}
__device__ __forceinline__ void cp_commit() { asm volatile("cp.async.commit_group;"); }
__device__ __forceinline__ void ldmatrix_x4(uint32_t& r0, uint32_t& r1, uint32_t& r2,
                                            uint32_t& r3, uint32_t addr) {
    asm volatile("ldmatrix.sync.aligned.m8n8.x4.shared.b16 {%0,%1,%2,%3}, [%4];"
                 : "=r"(r0), "=r"(r1), "=r"(r2), "=r"(r3) : "r"(addr));
}
__device__ __forceinline__ void ldmatrix_x4_t(uint32_t& r0, uint32_t& r1, uint32_t& r2,
                                              uint32_t& r3, uint32_t addr) {
    asm volatile("ldmatrix.sync.aligned.m8n8.x4.trans.shared.b16 {%0,%1,%2,%3}, [%4];"
                 : "=r"(r0), "=r"(r1), "=r"(r2), "=r"(r3) : "r"(addr));
}
__device__ __forceinline__ void mma16816(float* c, const uint32_t* a, const uint32_t* b) {
    asm volatile(
        "mma.sync.aligned.m16n8k16.row.col.f32.bf16.bf16.f32 "
        "{%0,%1,%2,%3}, {%4,%5,%6,%7}, {%8,%9}, {%0,%1,%2,%3};"
        : "+f"(c[0]), "+f"(c[1]), "+f"(c[2]), "+f"(c[3])
        : "r"(a[0]), "r"(a[1]), "r"(a[2]), "r"(a[3]), "r"(b[0]), "r"(b[1]));
}
__device__ __forceinline__ void split_bf16(float x, __nv_bfloat16& h, __nv_bfloat16& l) {
    h = __float2bfloat16(x);
    l = __float2bfloat16(x - __bfloat162float(h));
}

// ================= HMMA split-bf16 GEMM, 128x256 tile, 4-stage =================
#define APAD 40
#define GSTG 4
#define ASTG (128 * APAD * 2)                 // 10240
#define BSTG (256 * APAD * 2)                 // 20480
#define GEMM_SMEM (GSTG * (ASTG + BSTG))      // 122880

__global__ __launch_bounds__(256, 1) void mma_gemm(
    const __nv_bfloat16* __restrict__ A, const __nv_bfloat16* __restrict__ Bt,
    float* __restrict__ C, int N, int K3)
{
    extern __shared__ char gsm[];
    const uint32_t sA = smem_u32(gsm);
    const uint32_t sB = sA + GSTG * ASTG;

    const int tid = threadIdx.x, wid = tid >> 5, lane = tid & 31;
    const int bm = blockIdx.y << 7, bn = blockIdx.x << 8;
    const int wm = (wid & 1) << 6;            // 0 / 64
    const int wn = (wid >> 1) << 6;           // 0 / 64 / 128 / 192
    const __nv_bfloat16* Ab = A + (size_t)bm * K3;
    const __nv_bfloat16* Bb = Bt + (size_t)bn * K3;
    const int nk = K3 >> 5;

    float acc[4][8][4];
#pragma unroll
    for (int i = 0; i < 4; i++)
#pragma unroll
        for (int j = 0; j < 8; j++)
#pragma unroll
            for (int k = 0; k < 4; k++) acc[i][j][k] = 0.f;

#define LOAD_STAGE(kt, s) do {                                                        \
    size_t kb = (size_t)(kt) << 5;                                                    \
    _Pragma("unroll")                                                                 \
    for (int q = 0; q < 2; q++) {                                                     \
        int idx = tid + (q << 8); int r = idx >> 2, c8 = (idx & 3) << 3;              \
        cp_async16(sA + (s) * ASTG + (r * APAD + c8) * 2,                             \
                   Ab + (size_t)r * K3 + kb + c8);                                    \
    }                                                                                 \
    _Pragma("unroll")                                                                 \
    for (int q = 0; q < 4; q++) {                                                     \
        int idx = tid + (q << 8); int r = idx >> 2, c8 = (idx & 3) << 3;              \
        cp_async16(sB + (s) * BSTG + (r * APAD + c8) * 2,                             \
                   Bb + (size_t)r * K3 + kb + c8);                                    \
    }                                                                                 \
} while (0)

    LOAD_STAGE(0, 0); cp_commit();
    LOAD_STAGE(1, 1); cp_commit();
    LOAD_STAGE(2, 2); cp_commit();

    const int a_row = wm + (lane & 15);
    const int a_col = (lane >> 4) << 3;
    const int b_row = ((lane >> 4) & 1) * 8 + (lane & 7);
    const int b_col = ((lane >> 3) & 1) << 3;

    for (int kt = 0; kt < nk; kt++) {
        asm volatile("cp.async.wait_group 2;");
        __syncthreads();
        if (kt + 3 < nk) LOAD_STAGE(kt + 3, (kt + 3) & (GSTG - 1));
        cp_commit();

        const int s = kt & (GSTG - 1);
        const uint32_t aBase = sA + s * ASTG;
        const uint32_t bBase = sB + s * BSTG;
#pragma unroll
        for (int ks = 0; ks < 2; ks++) {
            uint32_t a[4][4], b[4][4];
#pragma unroll
            for (int mi = 0; mi < 4; mi++)
                ldmatrix_x4(a[mi][0], a[mi][1], a[mi][2], a[mi][3],
                            aBase + 2 * ((a_row + mi * 16) * APAD + ks * 16 + a_col));
#pragma unroll
            for (int nj = 0; nj < 4; nj++)
                ldmatrix_x4(b[nj][0], b[nj][1], b[nj][2], b[nj][3],
                            bBase + 2 * ((wn + nj * 16 + b_row) * APAD + ks * 16 + b_col));
#pragma unroll
            for (int mi = 0; mi < 4; mi++)
#pragma unroll
                for (int nt = 0; nt < 8; nt++)
                    mma16816(acc[mi][nt], a[mi], &b[nt >> 1][(nt & 1) * 2]);
        }
    }

    const int g = lane >> 2, tl = lane & 3;
#pragma unroll
    for (int mi = 0; mi < 4; mi++) {
#pragma unroll
        for (int nt = 0; nt < 8; nt++) {
            int row = bm + wm + mi * 16 + g;
            int col = bn + wn + nt * 8 + tl * 2;
            *(float2*)(C + (size_t)row * N + col) =
                make_float2(acc[mi][nt][0], acc[mi][nt][1]);
            *(float2*)(C + (size_t)(row + 8) * N + col) =
                make_float2(acc[mi][nt][2], acc[mi][nt][3]);
        }
    }
#undef LOAD_STAGE
}

// ================= conversion kernels =================
__global__ __launch_bounds__(256) void conv_cat_A(
    const float* __restrict__ X, __nv_bfloat16* __restrict__ Y, int K)
{
    const int row = blockIdx.x;
    const float* xr = X + (size_t)row * K;
    __nv_bfloat16* yr = Y + (size_t)row * 3 * K;
    for (int c = threadIdx.x; c < K; c += 256) {
        __nv_bfloat16 h, l;
        split_bf16(xr[c], h, l);
        yr[c] = h; yr[K + c] = l; yr[2 * K + c] = h;
    }
}
__global__ __launch_bounds__(256) void convT_cat_B(
    const float* __restrict__ W, __nv_bfloat16* __restrict__ Y, int K, int N)
{
    __shared__ float s[32][33];
    const int tx = threadIdx.x & 31, ty = threadIdx.x >> 5;
    const int n0 = blockIdx.x << 5, k0 = blockIdx.y << 5;
#pragma unroll
    for (int i = 0; i < 4; i++)
        s[ty + 8 * i][tx] = W[(size_t)(k0 + ty + 8 * i) * N + n0 + tx];
    __syncthreads();
#pragma unroll
    for (int i = 0; i < 4; i++) {
        int n = n0 + ty + 8 * i, k = k0 + tx;
        __nv_bfloat16 h, l;
        split_bf16(s[tx][ty + 8 * i], h, l);
        __nv_bfloat16* yr = Y + (size_t)n * 3 * K;
        yr[k] = h; yr[K + k] = h; yr[2 * K + k] = l;
    }
}
__global__ __launch_bounds__(256) void conv_q(
    const float* __restrict__ Q, __nv_bfloat16* __restrict__ Qh, __nv_bfloat16* __restrict__ Ql)
{
    const size_t base = (size_t)blockIdx.x * 4096;
    for (int c = threadIdx.x; c < 4096; c += 256) {
        __nv_bfloat16 h, l;
        split_bf16(Q[base + c], h, l);
        Qh[base + c] = h; Ql[base + c] = l;
    }
}
__global__ __launch_bounds__(256) void conv_kvb(
    const float* __restrict__ KVB, const float* __restrict__ KPE,
    __nv_bfloat16* __restrict__ Kh, __nv_bfloat16* __restrict__ Kl,
    __nv_bfloat16* __restrict__ Vh, __nv_bfloat16* __restrict__ Vl)
{
    const int row = blockIdx.x;
    const size_t kvb = (size_t)row * 2048, kpe = (size_t)row * 128;
    for (int t = threadIdx.x; t < 2048; t += 256) {
        int kvh = t >> 8, d = t & 255;
        float v = (d < 128) ? KVB[kvb + kvh * 256 + d] : KPE[kpe + (d - 128)];
        __nv_bfloat16 h, l;
        split_bf16(v, h, l);
        Kh[(size_t)row * 2048 + t] = h;
        Kl[(size_t)row * 2048 + t] = l;
    }
    for (int t = threadIdx.x; t < 1024; t += 256) {
        int kvh = t >> 7, d = t & 127;
        float v = KVB[kvb + kvh * 256 + 128 + d];
        __nv_bfloat16 h, l;
        split_bf16(v, h, l);
        Vh[(size_t)row * 1024 + t] = h;
        Vl[(size_t)row * 1024 + t] = l;
    }
}

// ---------------- rope cos/sin table ----------------
__global__ void rope_table_kernel(const int* __restrict__ pos,
                                  float* __restrict__ cosT, float* __restrict__ sinT)
{
    int s = blockIdx.x, i = threadIdx.x;
    double e = (double)i / 64.0;
    float t = (float)pow(10000.0, e);
    float freq = (1.0f / t) * 40.0f;
    float ang = (float)pos[s] * freq;
    cosT[s * 64 + i] = (float)cos((double)ang);
    sinT[s * 64 + i] = (float)sin((double)ang);
}

// ---------------- layernorm + rope ----------------
__global__ __launch_bounds__(256) void ln_rope_kernel(
    const float* __restrict__ KV, const float* __restrict__ lnscale,
    float* __restrict__ Q, __nv_bfloat16* __restrict__ KVCc, float* __restrict__ KPE,
    const float* __restrict__ cosT, const float* __restrict__ sinT)
{
    const int row = blockIdx.x;
    const int tid = threadIdx.x;
    const int s = row & (S_ - 1);
    const float* kvr = KV + (size_t)row * 768;

    float v0 = kvr[tid], v1 = kvr[tid + 256];
    float sum = v0 + v1, sq = v0 * v0 + v1 * v1;
#pragma unroll
    for (int o = 16; o > 0; o >>= 1) {
        sum += __shfl_xor_sync(0xffffffffu, sum, o);
        sq  += __shfl_xor_sync(0xffffffffu, sq, o);
    }
    __shared__ float red[16];
    if ((tid & 31) == 0) { red[tid >> 5] = sum; red[(tid >> 5) + 8] = sq; }
    __syncthreads();
    float tot = 0.f, tot2 = 0.f;
#pragma unroll
    for (int i = 0; i < 8; i++) { tot += red[i]; tot2 += red[i + 8]; }
    float mean = tot * (1.f / 512.f);
    float var  = tot2 * (1.f / 512.f) - mean * mean;
    float inv  = rsqrtf(var + 1e-5f);
    float y0 = (v0 - mean) * inv * lnscale[tid];
    float y1 = (v1 - mean) * inv * lnscale[tid + 256];
    {
        __nv_bfloat16 h, l;
        __nv_bfloat16* yr = KVCc + (size_t)row * 1536;
        split_bf16(y0, h, l);
        yr[tid] = h; yr[512 + tid] = l; yr[1024 + tid] = h;
        split_bf16(y1, h, l);
        yr[tid + 256] = h; yr[512 + tid + 256] = l; yr[1024 + tid + 256] = h;
    }

    if (tid < 64) {
        float c = cosT[s * 64 + tid], sn = sinT[s * 64 + tid];
        float xr = kvr[512 + 2 * tid], xi = kvr[512 + 2 * tid + 1];
        KPE[(size_t)row * 128 + 2 * tid]     = xr * c - xi * sn;
        KPE[(size_t)row * 128 + 2 * tid + 1] = xr * sn + xi * c;
    }
#pragma unroll
    for (int t = tid; t < 1024; t += 256) {
        int hh = t >> 6, i = t & 63;
        float c = cosT[s * 64 + i], sn = sinT[s * 64 + i];
        float* qp = Q + (size_t)row * 4096 + hh * 256 + 128 + 2 * i;
        float xr = qp[0], xi = qp[1];
        qp[0] = xr * c - xi * sn;
        qp[1] = xr * sn + xi * c;
    }
}

// ================= flash attention: HMMA, split-bf16, pipelined =================
#define FQ_H   0
#define FQ_L   16896
#define FK_H   33792
#define FK_L   50688
#define FV_H   67584          // [64][136]
#define FV_L   76288
#define FP_H   84992          // [64][72]
#define FP_L   89600
#define FS_B   188416         // S [64][68] fp32 (byte offset)
#define FA_B   205824
#define FL_B   206080
#define FLASH2_SMEM 206336

__global__ __launch_bounds__(256) void flash2_kernel(
    const __nv_bfloat16* __restrict__ Qh, const __nv_bfloat16* __restrict__ Ql,
    const __nv_bfloat16* __restrict__ Kh, const __nv_bfloat16* __restrict__ Kl,
    const __nv_bfloat16* __restrict__ Vh, const __nv_bfloat16* __restrict__ Vl,
    __nv_bfloat16* __restrict__ ATTNc)
{
    extern __shared__ __nv_bfloat16 sm[];
    const uint32_t sb = smem_u32(sm);
    float* Ssm  = (float*)((char*)sm + FS_B);
    float* Asm  = (float*)((char*)sm + FA_B);
    float* Lsm  = (float*)((char*)sm + FL_B);

    const int tid = threadIdx.x, wid = tid >> 5, lane = tid & 31;
    const int qi = 31 - blockIdx.x;       // heavy tiles first
    const int hh = blockIdx.y, b = blockIdx.z;
    const int kvh = hh >> 1;
    const int qb = b * S_ + qi * 64;

#define LOAD_K(kb_) do {                                                        \
    for (int idx = tid; idx < 2048; idx += 256) {                               \
        int row = idx >> 5, c8 = (idx & 31) << 3;                               \
        const size_t gk = (size_t)((kb_) + row) * 2048 + kvh * 256 + c8;        \
        cp_async16(sb + (FK_H + row * 264 + c8) * 2, Kh + gk);                  \
        cp_async16(sb + (FK_L + row * 264 + c8) * 2, Kl + gk);                  \
    } } while (0)
#define LOAD_V(kb_) do {                                                        \
    for (int idx = tid; idx < 1024; idx += 256) {                               \
        int row = idx >> 4, c8 = (idx & 15) << 3;                               \
        const size_t gv = (size_t)((kb_) + row) * 1024 + kvh * 128 + c8;        \
        cp_async16(sb + (FV_H + row * 136 + c8) * 2, Vh + gv);                  \
        cp_async16(sb + (FV_L + row * 136 + c8) * 2, Vl + gv);                  \
    } } while (0)

    // prologue: K(0), Q, V(0)
    LOAD_K(b * S_); cp_commit();
    for (int idx = tid; idx < 2048; idx += 256) {
        int row = idx >> 5, c8 = (idx & 31) << 3;
        const size_t g = (size_t)(qb + row) * 4096 + hh * 256 + c8;
        cp_async16(sb + (FQ_H + row * 264 + c8) * 2, Qh + g);
        cp_async16(sb + (FQ_L + row * 264 + c8) * 2, Ql + g);
    }
    cp_commit();
    LOAD_V(b * S_); cp_commit();
    asm volatile("cp.async.wait_group 1;");
    __syncthreads();

    const int srow = wid * 8 + (lane >> 2);
    const int stl = lane & 3;
    float m = -INFINITY, lacc = 0.f;

    const int wmS = (wid & 3) << 4, wnS = (wid >> 2) << 5;
    const int vm = (wid & 3) << 4, vn = (wid >> 2) << 6;

    const int a_row = lane & 15, a_colo = (lane >> 4) << 3;
    const int b_row = ((lane >> 4) & 1) * 8 + (lane & 7);
    const int b_col = ((lane >> 3) & 1) << 3;
    const int g = lane >> 2, tl = lane & 3;

    float oacc[8][4];
#pragma unroll
    for (int i = 0; i < 8; i++)
#pragma unroll
        for (int j = 0; j < 4; j++) oacc[i][j] = 0.f;

    const float scale = 0.08838834764831845f;

    for (int kt = 0; kt <= qi; kt++) {
        const bool has_next = (kt < qi);
        const int kb_next = b * S_ + (kt + 1) * 64;

        // ---- S = Q K^T, merged 3-combo split (hh + lh + hl) ----
        float sacc[4][4];
#pragma unroll
        for (int i = 0; i < 4; i++)
#pragma unroll
            for (int j = 0; j < 4; j++) sacc[i][j] = 0.f;
#pragma unroll
        for (int kc = 0; kc < 16; kc++) {
            uint32_t qh[4], ql[4], kh[2][4], kl[2][4];
            ldmatrix_x4(qh[0], qh[1], qh[2], qh[3],
                        sb + FQ_H * 2 + 2 * ((wmS + a_row) * 264 + kc * 16 + a_colo));
            ldmatrix_x4(ql[0], ql[1], ql[2], ql[3],
                        sb + FQ_L * 2 + 2 * ((wmS + a_row) * 264 + kc * 16 + a_colo));
#pragma unroll
            for (int nj = 0; nj < 2; nj++) {
                ldmatrix_x4(kh[nj][0], kh[nj][1], kh[nj][2], kh[nj][3],
                            sb + FK_H * 2 + 2 * ((wnS + nj * 16 + b_row) * 264 + kc * 16 + b_col));
                ldmatrix_x4(kl[nj][0], kl[nj][1], kl[nj][2], kl[nj][3],
                            sb + FK_L * 2 + 2 * ((wnS + nj * 16 + b_row) * 264 + kc * 16 + b_col));
            }
#pragma unroll
            for (int nt = 0; nt < 4; nt++) {
                mma16816(sacc[nt], qh, &kh[nt >> 1][(nt & 1) * 2]);
                mma16816(sacc[nt], ql, &kh[nt >> 1][(nt & 1) * 2]);
                mma16816(sacc[nt], qh, &kl[nt >> 1][(nt & 1) * 2]);
            }
        }
#pragma unroll
        for (int nt = 0; nt < 4; nt++) {
            int col = wnS + nt * 8 + tl * 2;
            *(float2*)(Ssm + (wmS + g) * 68 + col) = make_float2(sacc[nt][0], sacc[nt][1]);
            *(float2*)(Ssm + (wmS + g + 8) * 68 + col) = make_float2(sacc[nt][2], sacc[nt][3]);
        }
        __syncthreads();                       // K smem free, S staged

        // ---- prefetch K(kt+1) ----
        if (has_next) { LOAD_K(kb_next); }
        cp_commit();

        // ---- softmax (fp32), P split to bf16 hi/lo ----
        {
            float sv[16];
            const bool diag = (kt == qi);
#pragma unroll
            for (int j = 0; j < 16; j++) {
                int c = stl + 4 * j;
                float v = Ssm[srow * 68 + c] * scale;
                if (diag && c > srow) v = -INFINITY;
                sv[j] = v;
            }
            float mt = sv[0];
#pragma unroll
            for (int j = 1; j < 16; j++) mt = fmaxf(mt, sv[j]);
            mt = fmaxf(mt, __shfl_xor_sync(0xffffffffu, mt, 1));
            mt = fmaxf(mt, __shfl_xor_sync(0xffffffffu, mt, 2));
            float mnew = fmaxf(m, mt);
            float alpha = __expf(m - mnew);
            float rs = 0.f;
            __nv_bfloat16* PhS = sm + FP_H + srow * 72;
            __nv_bfloat16* PlS = sm + FP_L + srow * 72;
#pragma unroll
            for (int j = 0; j < 16; j++) {
                float p = __expf(sv[j] - mnew);
                rs += p;
                __nv_bfloat16 hb, lb;
                split_bf16(p, hb, lb);
                int c = stl + 4 * j;
                PhS[c] = hb; PlS[c] = lb;
            }
            rs += __shfl_xor_sync(0xffffffffu, rs, 1);
            rs += __shfl_xor_sync(0xffffffffu, rs, 2);
            lacc = lacc * alpha + rs;
            m = mnew;
            if (stl == 0) Asm[srow] = alpha;
        }
        __syncthreads();                       // P, alpha visible

        // ---- wait V(kt) ----
        asm volatile("cp.async.wait_group 1;");
        __syncthreads();

        // ---- O = O*alpha + P V, merged 3-combo split ----
        {
            float ag = Asm[vm + g], ag8 = Asm[vm + g + 8];
#pragma unroll
            for (int nt = 0; nt < 8; nt++) {
                oacc[nt][0] *= ag;  oacc[nt][1] *= ag;
                oacc[nt][2] *= ag8; oacc[nt][3] *= ag8;
            }
#pragma unroll
            for (int kc = 0; kc < 4; kc++) {
                uint32_t ph[4], pl[4], vhf[4][4], vlf[4][4];
                ldmatrix_x4(ph[0], ph[1], ph[2], ph[3],
                            sb + FP_H * 2 + 2 * ((vm + a_row) * 72 + kc * 16 + a_colo));
                ldmatrix_x4(pl[0], pl[1], pl[2], pl[3],
                            sb + FP_L * 2 + 2 * ((vm + a_row) * 72 + kc * 16 + a_colo));
#pragma unroll
                for (int nj = 0; nj < 4; nj++) {
                    ldmatrix_x4_t(vhf[nj][0], vhf[nj][1], vhf[nj][2], vhf[nj][3],
                                  sb + FV_H * 2 + 2 * ((kc * 16 + (lane & 15)) * 136 +
                                                       vn + nj * 16 + a_colo));
                    ldmatrix_x4_t(vlf[nj][0], vlf[nj][1], vlf[nj][2], vlf[nj][3],
                                  sb + FV_L * 2 + 2 * ((kc * 16 + (lane & 15)) * 136 +
                                                       vn + nj * 16 + a_colo));
                }
#pragma unroll
                for (int nt = 0; nt < 8; nt++) {
                    mma16816(oacc[nt], ph, &vhf[nt >> 1][(nt & 1) * 2]);
                    mma16816(oacc[nt], pl, &vhf[nt >> 1][(nt & 1) * 2]);
                    mma16816(oacc[nt], ph, &vlf[nt >> 1][(nt & 1) * 2]);
                }
            }
        }
        __syncthreads();                       // V, P free

        // ---- prefetch V(kt+1); wait K(kt+1) ----
        if (has_next) {
            LOAD_V(kb_next); cp_commit();
            asm volatile("cp.async.wait_group 1;");
            __syncthreads();
        }
    }

    // ---- epilogue ----
    if (stl == 0) Lsm[srow] = 1.f / lacc;
    __syncthreads();
    {
        float lg = Lsm[vm + g], lg8 = Lsm[vm + g + 8];
#pragma unroll
        for (int nt = 0; nt < 8; nt++) {
            int col = vn + nt * 8 + tl * 2;
            float v0 = oacc[nt][0] * lg,  v1 = oacc[nt][1] * lg;
            float v2 = oacc[nt][2] * lg8, v3 = oacc[nt][3] * lg8;
            __nv_bfloat16 h0, l0, h1, l1;
            __nv_bfloat16* base0 = ATTNc + (size_t)(qb + vm + g) * 6144 + hh * 128;
            split_bf16(v0, h0, l0); split_bf16(v1, h1, l1);
            *(__nv_bfloat162*)(base0 + col)        = __nv_bfloat162(h0, h1);
            *(__nv_bfloat162*)(base0 + 2048 + col) = __nv_bfloat162(l0, l1);
            *(__nv_bfloat162*)(base0 + 4096 + col) = __nv_bfloat162(h0, h1);
            __nv_bfloat16* base1 = ATTNc + (size_t)(qb + vm + g + 8) * 6144 + hh * 128;
            split_bf16(v2, h0, l0); split_bf16(v3, h1, l1);
            *(__nv_bfloat162*)(base1 + col)        = __nv_bfloat162(h0, h1);
            *(__nv_bfloat162*)(base1 + 2048 + col) = __nv_bfloat162(l0, l1);
            *(__nv_bfloat162*)(base1 + 4096 + col) = __nv_bfloat162(h0, h1);
        }
    }
#undef LOAD_K
#undef LOAD_V
}

// ---------------- launcher ----------------
extern "C" void kernel_launch(void* const* d_in, const int* in_sizes, int n_in,
                              void* d_out, int out_size)
{
    const float* x        = (const float*)d_in[0];
    const float* wq       = (const float*)d_in[1];
    const float* wkv_a    = (const float*)d_in[2];
    const float* kv_scale = (const float*)d_in[3];
    const float* wkv_b    = (const float*)d_in[4];
    const float* wo       = (const float*)d_in[5];
    const int* pos        = (const int*)d_in[7];
    float* out            = (float*)d_out;

    float *Q, *KV, *KPE, *KVB, *cosT, *sinT;
    __nv_bfloat16 *Xc, *KVCc, *ATTNc, *WqT, *WkvaT, *WkvbT, *WoT;
    __nv_bfloat16 *Qh, *Ql, *Kh, *Kl, *Vh, *Vl;
    cudaGetSymbolAddress((void**)&Q,     g_Q);
    cudaGetSymbolAddress((void**)&KV,    g_KV);
    cudaGetSymbolAddress((void**)&KPE,   g_KPE);
    cudaGetSymbolAddress((void**)&KVB,   g_KVB);
    cudaGetSymbolAddress((void**)&cosT,  g_COS);
    cudaGetSymbolAddress((void**)&sinT,  g_SIN);
    cudaGetSymbolAddress((void**)&Xc,    g_Xc);
    cudaGetSymbolAddress((void**)&KVCc,  g_KVCc);
    cudaGetSymbolAddress((void**)&ATTNc, g_ATTNc);
    cudaGetSymbolAddress((void**)&WqT,   g_WqT);
    cudaGetSymbolAddress((void**)&WkvaT, g_WkvaT);
    cudaGetSymbolAddress((void**)&WkvbT, g_WkvbT);
    cudaGetSymbolAddress((void**)&WoT,   g_WoT);
    cudaGetSymbolAddress((void**)&Qh,    g_Qh);
    cudaGetSymbolAddress((void**)&Ql,    g_Ql);
    cudaGetSymbolAddress((void**)&Kh,    g_Kh);
    cudaGetSymbolAddress((void**)&Kl,    g_Kl);
    cudaGetSymbolAddress((void**)&Vh,    g_Vh);
    cudaGetSymbolAddress((void**)&Vl,    g_Vl);

    cudaFuncSetAttribute(flash2_kernel,
                         cudaFuncAttributeMaxDynamicSharedMemorySize, FLASH2_SMEM);
    cudaFuncSetAttribute(mma_gemm,
                         cudaFuncAttributeMaxDynamicSharedMemorySize, GEMM_SMEM);

    dim3 blk(256);
    conv_cat_A<<<NROWS, blk>>>(x, Xc, 2048);
    convT_cat_B<<<dim3(4096 / 32, 2048 / 32), blk>>>(wq, WqT, 2048, 4096);
    convT_cat_B<<<dim3(640 / 32, 2048 / 32), blk>>>(wkv_a, WkvaT, 2048, 640);
    convT_cat_B<<<dim3(2048 / 32, 512 / 32), blk>>>(wkv_b, WkvbT, 512, 2048);
    convT_cat_B<<<dim3(2048 / 32, 2048 / 32), blk>>>(wo, WoT, 2048, 2048);
    rope_table_kernel<<<S_, 64>>>(pos, cosT, sinT);
    mma_gemm<<<dim3(16, 32), blk, GEMM_SMEM>>>(Xc, WqT, Q, 4096, 6144);       // q proj
    mma_gemm<<<dim3(3, 32), blk, GEMM_SMEM>>>(Xc, WkvaT, KV, 768, 6144);      // kv_a proj
    ln_rope_kernel<<<NROWS, blk>>>(KV, kv_scale, Q, KVCc, KPE, cosT, sinT);
    mma_gemm<<<dim3(8, 32), blk, GEMM_SMEM>>>(KVCc, WkvbT, KVB, 2048, 1536);  // kv_b proj
    conv_q<<<NROWS, blk>>>(Q, Qh, Ql);
    conv_kvb<<<NROWS, blk>>>(KVB, KPE, Kh, Kl, Vh, Vl);
    flash2_kernel<<<dim3(32, H_, B_), blk, FLASH2_SMEM>>>(Qh, Ql, Kh, Kl, Vh, Vl, ATTNc);
    mma_gemm<<<dim3(8, 32), blk, GEMM_SMEM>>>(ATTNc, WoT, out, 2048, 6144);   // out proj
}

// round 7
// speedup vs baseline: 1.1006x; 1.1006x over previous
#include <cuda_runtime.h>
#include <cuda_bf16.h>
#include <cstdint>
#include <math.h>

#define B_    2
#define S_    2048
#define H_    16
#define NROWS 4096          // B_*S_

// ---------------- scratch (device globals: no allocs allowed) ----------------
__device__ float g_Q[NROWS * 4096];                  // (b,s,h,256) nope|rope(pe)  fp32
__device__ float g_KV[NROWS * 768];                  // x @ wkv_a (padded 640->768)
__device__ float g_KPE[NROWS * 128];                 // roped k_pe
__device__ float g_KVB[NROWS * 2048];                // (b,s,kvh,256) k_nope|v fp32
__device__ float g_COS[S_ * 64];
__device__ float g_SIN[S_ * 64];
// bf16 split-cat buffers (GEMMs): A=[hi,lo,hi], B(transposed)=[hi,hi,lo]
__device__ __nv_bfloat16 g_Xc[NROWS * 6144];
__device__ __nv_bfloat16 g_KVCc[NROWS * 1536];
__device__ __nv_bfloat16 g_ATTNc[NROWS * 6144];
__device__ __nv_bfloat16 g_WqT[4096 * 6144];
__device__ __nv_bfloat16 g_WkvaT[768 * 6144];
__device__ __nv_bfloat16 g_WkvbT[2048 * 1536];
__device__ __nv_bfloat16 g_WoT[2048 * 6144];
// bf16 hi/lo planes for flash attention
__device__ __nv_bfloat16 g_Qh[NROWS * 4096];         // (b,s,h,256)
__device__ __nv_bfloat16 g_Ql[NROWS * 4096];
__device__ __nv_bfloat16 g_Kh[NROWS * 2048];         // (b,s,kvh,256) nope|pe
__device__ __nv_bfloat16 g_Kl[NROWS * 2048];
__device__ __nv_bfloat16 g_Vh[NROWS * 1024];         // (b,s,kvh,128)
__device__ __nv_bfloat16 g_Vl[NROWS * 1024];

// ================= helpers =================
__device__ __forceinline__ uint32_t smem_u32(const void* p) {
    uint32_t a;
    asm("{ .reg .u64 t; cvta.to.shared.u64 t, %1; cvt.u32.u64 %0, t; }" : "=r"(a) : "l"(p));
    return a;
}
__device__ __forceinline__ void cp_async16(uint32_t saddr, const void* gaddr) {
    asm volatile("cp.async.cg.shared.global [%0], [%1], 16;" :: "r"(saddr), "l"(gaddr));
}
__device__ __forceinline__ void cp_commit() { asm volatile("cp.async.commit_group;"); }
__device__ __forceinline__ void ldmatrix_x4(uint32_t& r0, uint32_t& r1, uint32_t& r2,
                                            uint32_t& r3, uint32_t addr) {
    asm volatile("ldmatrix.sync.aligned.m8n8.x4.shared.b16 {%0,%1,%2,%3}, [%4];"
                 : "=r"(r0), "=r"(r1), "=r"(r2), "=r"(r3) : "r"(addr));
}
__device__ __forceinline__ void ldmatrix_x4_t(uint32_t& r0, uint32_t& r1, uint32_t& r2,
                                              uint32_t& r3, uint32_t addr) {
    asm volatile("ldmatrix.sync.aligned.m8n8.x4.trans.shared.b16 {%0,%1,%2,%3}, [%4];"
                 : "=r"(r0), "=r"(r1), "=r"(r2), "=r"(r3) : "r"(addr));
}
__device__ __forceinline__ void mma16816(float* c, const uint32_t* a, const uint32_t* b) {
    asm volatile(
        "mma.sync.aligned.m16n8k16.row.col.f32.bf16.bf16.f32 "
        "{%0,%1,%2,%3}, {%4,%5,%6,%7}, {%8,%9}, {%0,%1,%2,%3};"
        : "+f"(c[0]), "+f"(c[1]), "+f"(c[2]), "+f"(c[3])
        : "r"(a[0]), "r"(a[1]), "r"(a[2]), "r"(a[3]), "r"(b[0]), "r"(b[1]));
}
__device__ __forceinline__ void split_bf16(float x, __nv_bfloat16& h, __nv_bfloat16& l) {
    h = __float2bfloat16(x);
    l = __float2bfloat16(x - __bfloat162float(h));
}

// ================= HMMA split-bf16 GEMM, 128x128 tile, 4-stage (R5 proven) =================
#define APAD 40
#define GSTG 4
#define STG_BYTES (128 * APAD * 2)            // 10240 per operand per stage
#define GEMM_SMEM (GSTG * STG_BYTES * 2)      // 81920

__global__ __launch_bounds__(256) void mma_gemm(
    const __nv_bfloat16* __restrict__ A, const __nv_bfloat16* __restrict__ Bt,
    float* __restrict__ C, int N, int K3)
{
    extern __shared__ char gsm[];
    const uint32_t sA = smem_u32(gsm);
    const uint32_t sB = sA + GSTG * STG_BYTES;

    const int tid = threadIdx.x, wid = tid >> 5, lane = tid & 31;
    const int bm = blockIdx.y << 7, bn = blockIdx.x << 7;
    const int wm = (wid & 1) << 6;
    const int wn = (wid >> 1) << 5;
    const __nv_bfloat16* Ab = A + (size_t)bm * K3;
    const __nv_bfloat16* Bb = Bt + (size_t)bn * K3;
    const int nk = K3 >> 5;

    float acc[4][4][4];
#pragma unroll
    for (int i = 0; i < 4; i++)
#pragma unroll
        for (int j = 0; j < 4; j++)
#pragma unroll
            for (int k = 0; k < 4; k++) acc[i][j][k] = 0.f;

    const int r0 = tid >> 2, c0 = (tid & 3) << 3;
    const int r1 = (tid + 256) >> 2;

#define LOAD_STAGE(kt, s) do {                                                        \
    size_t kb = (size_t)(kt) << 5;                                                    \
    cp_async16(sA + (s) * STG_BYTES + (r0 * APAD + c0) * 2,                           \
               Ab + (size_t)r0 * K3 + kb + c0);                                       \
    cp_async16(sA + (s) * STG_BYTES + (r1 * APAD + c0) * 2,                           \
               Ab + (size_t)r1 * K3 + kb + c0);                                       \
    cp_async16(sB + (s) * STG_BYTES + (r0 * APAD + c0) * 2,                           \
               Bb + (size_t)r0 * K3 + kb + c0);                                       \
    cp_async16(sB + (s) * STG_BYTES + (r1 * APAD + c0) * 2,                           \
               Bb + (size_t)r1 * K3 + kb + c0);                                       \
} while (0)

    LOAD_STAGE(0, 0); cp_commit();
    LOAD_STAGE(1, 1); cp_commit();
    LOAD_STAGE(2, 2); cp_commit();

    const int a_row = wm + (lane & 15);
    const int a_col = (lane >> 4) << 3;
    const int b_row = ((lane >> 4) & 1) * 8 + (lane & 7);
    const int b_col = ((lane >> 3) & 1) << 3;

    for (int kt = 0; kt < nk; kt++) {
        asm volatile("cp.async.wait_group 2;");
        __syncthreads();
        if (kt + 3 < nk) LOAD_STAGE(kt + 3, (kt + 3) & (GSTG - 1));
        cp_commit();

        const int s = kt & (GSTG - 1);
        const uint32_t aBase = sA + s * STG_BYTES;
        const uint32_t bBase = sB + s * STG_BYTES;
#pragma unroll
        for (int ks = 0; ks < 2; ks++) {
            uint32_t a[4][4], b[2][4];
#pragma unroll
            for (int mi = 0; mi < 4; mi++)
                ldmatrix_x4(a[mi][0], a[mi][1], a[mi][2], a[mi][3],
                            aBase + 2 * ((a_row + mi * 16) * APAD + ks * 16 + a_col));
#pragma unroll
            for (int nj = 0; nj < 2; nj++)
                ldmatrix_x4(b[nj][0], b[nj][1], b[nj][2], b[nj][3],
                            bBase + 2 * ((wn + nj * 16 + b_row) * APAD + ks * 16 + b_col));
#pragma unroll
            for (int mi = 0; mi < 4; mi++)
#pragma unroll
                for (int nt = 0; nt < 4; nt++)
                    mma16816(acc[mi][nt], a[mi], &b[nt >> 1][(nt & 1) * 2]);
        }
    }

    const int g = lane >> 2, tl = lane & 3;
#pragma unroll
    for (int mi = 0; mi < 4; mi++) {
#pragma unroll
        for (int nt = 0; nt < 4; nt++) {
            int row = bm + wm + mi * 16 + g;
            int col = bn + wn + nt * 8 + tl * 2;
            *(float2*)(C + (size_t)row * N + col) =
                make_float2(acc[mi][nt][0], acc[mi][nt][1]);
            *(float2*)(C + (size_t)(row + 8) * N + col) =
                make_float2(acc[mi][nt][2], acc[mi][nt][3]);
        }
    }
#undef LOAD_STAGE
}

// ================= conversion kernels =================
__global__ __launch_bounds__(256) void conv_cat_A(
    const float* __restrict__ X, __nv_bfloat16* __restrict__ Y, int K)
{
    const int row = blockIdx.x;
    const float* xr = X + (size_t)row * K;
    __nv_bfloat16* yr = Y + (size_t)row * 3 * K;
    for (int c = threadIdx.x; c < K; c += 256) {
        __nv_bfloat16 h, l;
        split_bf16(xr[c], h, l);
        yr[c] = h; yr[K + c] = l; yr[2 * K + c] = h;
    }
}
__global__ __launch_bounds__(256) void convT_cat_B(
    const float* __restrict__ W, __nv_bfloat16* __restrict__ Y, int K, int N)
{
    __shared__ float s[32][33];
    const int tx = threadIdx.x & 31, ty = threadIdx.x >> 5;
    const int n0 = blockIdx.x << 5, k0 = blockIdx.y << 5;
#pragma unroll
    for (int i = 0; i < 4; i++)
        s[ty + 8 * i][tx] = W[(size_t)(k0 + ty + 8 * i) * N + n0 + tx];
    __syncthreads();
#pragma unroll
    for (int i = 0; i < 4; i++) {
        int n = n0 + ty + 8 * i, k = k0 + tx;
        __nv_bfloat16 h, l;
        split_bf16(s[tx][ty + 8 * i], h, l);
        __nv_bfloat16* yr = Y + (size_t)n * 3 * K;
        yr[k] = h; yr[K + k] = h; yr[2 * K + k] = l;
    }
}
__global__ __launch_bounds__(256) void conv_q(
    const float* __restrict__ Q, __nv_bfloat16* __restrict__ Qh, __nv_bfloat16* __restrict__ Ql)
{
    const size_t base = (size_t)blockIdx.x * 4096;
    for (int c = threadIdx.x; c < 4096; c += 256) {
        __nv_bfloat16 h, l;
        split_bf16(Q[base + c], h, l);
        Qh[base + c] = h; Ql[base + c] = l;
    }
}
__global__ __launch_bounds__(256) void conv_kvb(
    const float* __restrict__ KVB, const float* __restrict__ KPE,
    __nv_bfloat16* __restrict__ Kh, __nv_bfloat16* __restrict__ Kl,
    __nv_bfloat16* __restrict__ Vh, __nv_bfloat16* __restrict__ Vl)
{
    const int row = blockIdx.x;
    const size_t kvb = (size_t)row * 2048, kpe = (size_t)row * 128;
    for (int t = threadIdx.x; t < 2048; t += 256) {
        int kvh = t >> 8, d = t & 255;
        float v = (d < 128) ? KVB[kvb + kvh * 256 + d] : KPE[kpe + (d - 128)];
        __nv_bfloat16 h, l;
        split_bf16(v, h, l);
        Kh[(size_t)row * 2048 + t] = h;
        Kl[(size_t)row * 2048 + t] = l;
    }
    for (int t = threadIdx.x; t < 1024; t += 256) {
        int kvh = t >> 7, d = t & 127;
        float v = KVB[kvb + kvh * 256 + 128 + d];
        __nv_bfloat16 h, l;
        split_bf16(v, h, l);
        Vh[(size_t)row * 1024 + t] = h;
        Vl[(size_t)row * 1024 + t] = l;
    }
}

// ---------------- rope cos/sin table ----------------
__global__ void rope_table_kernel(const int* __restrict__ pos,
                                  float* __restrict__ cosT, float* __restrict__ sinT)
{
    int s = blockIdx.x, i = threadIdx.x;
    double e = (double)i / 64.0;
    float t = (float)pow(10000.0, e);
    float freq = (1.0f / t) * 40.0f;
    float ang = (float)pos[s] * freq;
    cosT[s * 64 + i] = (float)cos((double)ang);
    sinT[s * 64 + i] = (float)sin((double)ang);
}

// ---------------- layernorm + rope ----------------
__global__ __launch_bounds__(256) void ln_rope_kernel(
    const float* __restrict__ KV, const float* __restrict__ lnscale,
    float* __restrict__ Q, __nv_bfloat16* __restrict__ KVCc, float* __restrict__ KPE,
    const float* __restrict__ cosT, const float* __restrict__ sinT)
{
    const int row = blockIdx.x;
    const int tid = threadIdx.x;
    const int s = row & (S_ - 1);
    const float* kvr = KV + (size_t)row * 768;

    float v0 = kvr[tid], v1 = kvr[tid + 256];
    float sum = v0 + v1, sq = v0 * v0 + v1 * v1;
#pragma unroll
    for (int o = 16; o > 0; o >>= 1) {
        sum += __shfl_xor_sync(0xffffffffu, sum, o);
        sq  += __shfl_xor_sync(0xffffffffu, sq, o);
    }
    __shared__ float red[16];
    if ((tid & 31) == 0) { red[tid >> 5] = sum; red[(tid >> 5) + 8] = sq; }
    __syncthreads();
    float tot = 0.f, tot2 = 0.f;
#pragma unroll
    for (int i = 0; i < 8; i++) { tot += red[i]; tot2 += red[i + 8]; }
    float mean = tot * (1.f / 512.f);
    float var  = tot2 * (1.f / 512.f) - mean * mean;
    float inv  = rsqrtf(var + 1e-5f);
    float y0 = (v0 - mean) * inv * lnscale[tid];
    float y1 = (v1 - mean) * inv * lnscale[tid + 256];
    {
        __nv_bfloat16 h, l;
        __nv_bfloat16* yr = KVCc + (size_t)row * 1536;
        split_bf16(y0, h, l);
        yr[tid] = h; yr[512 + tid] = l; yr[1024 + tid] = h;
        split_bf16(y1, h, l);
        yr[tid + 256] = h; yr[512 + tid + 256] = l; yr[1024 + tid + 256] = h;
    }

    if (tid < 64) {
        float c = cosT[s * 64 + tid], sn = sinT[s * 64 + tid];
        float xr = kvr[512 + 2 * tid], xi = kvr[512 + 2 * tid + 1];
        KPE[(size_t)row * 128 + 2 * tid]     = xr * c - xi * sn;
        KPE[(size_t)row * 128 + 2 * tid + 1] = xr * sn + xi * c;
    }
#pragma unroll
    for (int t = tid; t < 1024; t += 256) {
        int hh = t >> 6, i = t & 63;
        float c = cosT[s * 64 + i], sn = sinT[s * 64 + i];
        float* qp = Q + (size_t)row * 4096 + hh * 256 + 128 + 2 * i;
        float xr = qp[0], xi = qp[1];
        qp[0] = xr * c - xi * sn;
        qp[1] = xr * sn + xi * c;
    }
}

// ================= flash attention: HMMA, split-bf16, pipelined, merged passes =================
#define FQ_H   0
#define FQ_L   16896
#define FK_H   33792
#define FK_L   50688
#define FV_H   67584          // [64][136]
#define FV_L   76288
#define FP_H   84992          // [64][72]
#define FP_L   89600
#define FS_B   188416         // S [64][68] fp32 (byte offset)
#define FA_B   205824
#define FL_B   206080
#define FLASH2_SMEM 206336

__global__ __launch_bounds__(256) void flash2_kernel(
    const __nv_bfloat16* __restrict__ Qh, const __nv_bfloat16* __restrict__ Ql,
    const __nv_bfloat16* __restrict__ Kh, const __nv_bfloat16* __restrict__ Kl,
    const __nv_bfloat16* __restrict__ Vh, const __nv_bfloat16* __restrict__ Vl,
    __nv_bfloat16* __restrict__ ATTNc)
{
    extern __shared__ __nv_bfloat16 sm[];
    const uint32_t sb = smem_u32(sm);
    float* Ssm  = (float*)((char*)sm + FS_B);
    float* Asm  = (float*)((char*)sm + FA_B);
    float* Lsm  = (float*)((char*)sm + FL_B);

    const int tid = threadIdx.x, wid = tid >> 5, lane = tid & 31;
    const int qi = 31 - blockIdx.x;       // heavy tiles first
    const int hh = blockIdx.y, b = blockIdx.z;
    const int kvh = hh >> 1;
    const int qb = b * S_ + qi * 64;

#define LOAD_K(kb_) do {                                                        \
    for (int idx = tid; idx < 2048; idx += 256) {                               \
        int row = idx >> 5, c8 = (idx & 31) << 3;                               \
        const size_t gk = (size_t)((kb_) + row) * 2048 + kvh * 256 + c8;        \
        cp_async16(sb + (FK_H + row * 264 + c8) * 2, Kh + gk);                  \
        cp_async16(sb + (FK_L + row * 264 + c8) * 2, Kl + gk);                  \
    } } while (0)
#define LOAD_V(kb_) do {                                                        \
    for (int idx = tid; idx < 1024; idx += 256) {                               \
        int row = idx >> 4, c8 = (idx & 15) << 3;                               \
        const size_t gv = (size_t)((kb_) + row) * 1024 + kvh * 128 + c8;        \
        cp_async16(sb + (FV_H + row * 136 + c8) * 2, Vh + gv);                  \
        cp_async16(sb + (FV_L + row * 136 + c8) * 2, Vl + gv);                  \
    } } while (0)

    // prologue: K(0), Q, V(0)
    LOAD_K(b * S_); cp_commit();
    for (int idx = tid; idx < 2048; idx += 256) {
        int row = idx >> 5, c8 = (idx & 31) << 3;
        const size_t g = (size_t)(qb + row) * 4096 + hh * 256 + c8;
        cp_async16(sb + (FQ_H + row * 264 + c8) * 2, Qh + g);
        cp_async16(sb + (FQ_L + row * 264 + c8) * 2, Ql + g);
    }
    cp_commit();
    LOAD_V(b * S_); cp_commit();
    asm volatile("cp.async.wait_group 1;");
    __syncthreads();

    const int srow = wid * 8 + (lane >> 2);
    const int stl = lane & 3;
    float m = -INFINITY, lacc = 0.f;

    const int wmS = (wid & 3) << 4, wnS = (wid >> 2) << 5;
    const int vm = (wid & 3) << 4, vn = (wid >> 2) << 6;

    const int a_row = lane & 15, a_colo = (lane >> 4) << 3;
    const int b_row = ((lane >> 4) & 1) * 8 + (lane & 7);
    const int b_col = ((lane >> 3) & 1) << 3;
    const int g = lane >> 2, tl = lane & 3;

    float oacc[8][4];
#pragma unroll
    for (int i = 0; i < 8; i++)
#pragma unroll
        for (int j = 0; j < 4; j++) oacc[i][j] = 0.f;

    const float scale = 0.08838834764831845f;

    for (int kt = 0; kt <= qi; kt++) {
        const bool has_next = (kt < qi);
        const int kb_next = b * S_ + (kt + 1) * 64;

        // ---- S = Q K^T, merged 3-combo split (hh + lh + hl) ----
        float sacc[4][4];
#pragma unroll
        for (int i = 0; i < 4; i++)
#pragma unroll
            for (int j = 0; j < 4; j++) sacc[i][j] = 0.f;
#pragma unroll
        for (int kc = 0; kc < 16; kc++) {
            uint32_t qh[4], ql[4], kh[2][4], kl[2][4];
            ldmatrix_x4(qh[0], qh[1], qh[2], qh[3],
                        sb + FQ_H * 2 + 2 * ((wmS + a_row) * 264 + kc * 16 + a_colo));
            ldmatrix_x4(ql[0], ql[1], ql[2], ql[3],
                        sb + FQ_L * 2 + 2 * ((wmS + a_row) * 264 + kc * 16 + a_colo));
#pragma unroll
            for (int nj = 0; nj < 2; nj++) {
                ldmatrix_x4(kh[nj][0], kh[nj][1], kh[nj][2], kh[nj][3],
                            sb + FK_H * 2 + 2 * ((wnS + nj * 16 + b_row) * 264 + kc * 16 + b_col));
                ldmatrix_x4(kl[nj][0], kl[nj][1], kl[nj][2], kl[nj][3],
                            sb + FK_L * 2 + 2 * ((wnS + nj * 16 + b_row) * 264 + kc * 16 + b_col));
            }
#pragma unroll
            for (int nt = 0; nt < 4; nt++) {
                mma16816(sacc[nt], qh, &kh[nt >> 1][(nt & 1) * 2]);
                mma16816(sacc[nt], ql, &kh[nt >> 1][(nt & 1) * 2]);
                mma16816(sacc[nt], qh, &kl[nt >> 1][(nt & 1) * 2]);
            }
        }
#pragma unroll
        for (int nt = 0; nt < 4; nt++) {
            int col = wnS + nt * 8 + tl * 2;
            *(float2*)(Ssm + (wmS + g) * 68 + col) = make_float2(sacc[nt][0], sacc[nt][1]);
            *(float2*)(Ssm + (wmS + g + 8) * 68 + col) = make_float2(sacc[nt][2], sacc[nt][3]);
        }
        __syncthreads();                       // K smem free, S staged

        // ---- prefetch K(kt+1) ----
        if (has_next) { LOAD_K(kb_next); }
        cp_commit();

        // ---- softmax (fp32), P split to bf16 hi/lo ----
        {
            float sv[16];
            const bool diag = (kt == qi);
#pragma unroll
            for (int j = 0; j < 16; j++) {
                int c = stl + 4 * j;
                float v = Ssm[srow * 68 + c] * scale;
                if (diag && c > srow) v = -INFINITY;
                sv[j] = v;
            }
            float mt = sv[0];
#pragma unroll
            for (int j = 1; j < 16; j++) mt = fmaxf(mt, sv[j]);
            mt = fmaxf(mt, __shfl_xor_sync(0xffffffffu, mt, 1));
            mt = fmaxf(mt, __shfl_xor_sync(0xffffffffu, mt, 2));
            float mnew = fmaxf(m, mt);
            float alpha = __expf(m - mnew);
            float rs = 0.f;
            __nv_bfloat16* PhS = sm + FP_H + srow * 72;
            __nv_bfloat16* PlS = sm + FP_L + srow * 72;
#pragma unroll
            for (int j = 0; j < 16; j++) {
                float p = __expf(sv[j] - mnew);
                rs += p;
                __nv_bfloat16 hb, lb;
                split_bf16(p, hb, lb);
                int c = stl + 4 * j;
                PhS[c] = hb; PlS[c] = lb;
            }
            rs += __shfl_xor_sync(0xffffffffu, rs, 1);
            rs += __shfl_xor_sync(0xffffffffu, rs, 2);
            lacc = lacc * alpha + rs;
            m = mnew;
            if (stl == 0) Asm[srow] = alpha;
        }
        __syncthreads();                       // P, alpha visible

        // ---- wait V(kt) ----
        asm volatile("cp.async.wait_group 1;");
        __syncthreads();

        // ---- O = O*alpha + P V, merged 3-combo split ----
        {
            float ag = Asm[vm + g], ag8 = Asm[vm + g + 8];
#pragma unroll
            for (int nt = 0; nt < 8; nt++) {
                oacc[nt][0] *= ag;  oacc[nt][1] *= ag;
                oacc[nt][2] *= ag8; oacc[nt][3] *= ag8;
            }
#pragma unroll
            for (int kc = 0; kc < 4; kc++) {
                uint32_t ph[4], pl[4], vhf[4][4], vlf[4][4];
                ldmatrix_x4(ph[0], ph[1], ph[2], ph[3],
                            sb + FP_H * 2 + 2 * ((vm + a_row) * 72 + kc * 16 + a_colo));
                ldmatrix_x4(pl[0], pl[1], pl[2], pl[3],
                            sb + FP_L * 2 + 2 * ((vm + a_row) * 72 + kc * 16 + a_colo));
#pragma unroll
                for (int nj = 0; nj < 4; nj++) {
                    ldmatrix_x4_t(vhf[nj][0], vhf[nj][1], vhf[nj][2], vhf[nj][3],
                                  sb + FV_H * 2 + 2 * ((kc * 16 + (lane & 15)) * 136 +
                                                       vn + nj * 16 + a_colo));
                    ldmatrix_x4_t(vlf[nj][0], vlf[nj][1], vlf[nj][2], vlf[nj][3],
                                  sb + FV_L * 2 + 2 * ((kc * 16 + (lane & 15)) * 136 +
                                                       vn + nj * 16 + a_colo));
                }
#pragma unroll
                for (int nt = 0; nt < 8; nt++) {
                    mma16816(oacc[nt], ph, &vhf[nt >> 1][(nt & 1) * 2]);
                    mma16816(oacc[nt], pl, &vhf[nt >> 1][(nt & 1) * 2]);
                    mma16816(oacc[nt], ph, &vlf[nt >> 1][(nt & 1) * 2]);
                }
            }
        }
        __syncthreads();                       // V, P free

        // ---- prefetch V(kt+1); wait K(kt+1) ----
        if (has_next) {
            LOAD_V(kb_next); cp_commit();
            asm volatile("cp.async.wait_group 1;");
            __syncthreads();
        }
    }

    // ---- epilogue ----
    if (stl == 0) Lsm[srow] = 1.f / lacc;
    __syncthreads();
    {
        float lg = Lsm[vm + g], lg8 = Lsm[vm + g + 8];
#pragma unroll
        for (int nt = 0; nt < 8; nt++) {
            int col = vn + nt * 8 + tl * 2;
            float v0 = oacc[nt][0] * lg,  v1 = oacc[nt][1] * lg;
            float v2 = oacc[nt][2] * lg8, v3 = oacc[nt][3] * lg8;
            __nv_bfloat16 h0, l0, h1, l1;
            __nv_bfloat16* base0 = ATTNc + (size_t)(qb + vm + g) * 6144 + hh * 128;
            split_bf16(v0, h0, l0); split_bf16(v1, h1, l1);
            *(__nv_bfloat162*)(base0 + col)        = __nv_bfloat162(h0, h1);
            *(__nv_bfloat162*)(base0 + 2048 + col) = __nv_bfloat162(l0, l1);
            *(__nv_bfloat162*)(base0 + 4096 + col) = __nv_bfloat162(h0, h1);
            __nv_bfloat16* base1 = ATTNc + (size_t)(qb + vm + g + 8) * 6144 + hh * 128;
            split_bf16(v2, h0, l0); split_bf16(v3, h1, l1);
            *(__nv_bfloat162*)(base1 + col)        = __nv_bfloat162(h0, h1);
            *(__nv_bfloat162*)(base1 + 2048 + col) = __nv_bfloat162(l0, l1);
            *(__nv_bfloat162*)(base1 + 4096 + col) = __nv_bfloat162(h0, h1);
        }
    }
#undef LOAD_K
#undef LOAD_V
}

// ---------------- launcher ----------------
extern "C" void kernel_launch(void* const* d_in, const int* in_sizes, int n_in,
                              void* d_out, int out_size)
{
    const float* x        = (const float*)d_in[0];
    const float* wq       = (const float*)d_in[1];
    const float* wkv_a    = (const float*)d_in[2];
    const float* kv_scale = (const float*)d_in[3];
    const float* wkv_b    = (const float*)d_in[4];
    const float* wo       = (const float*)d_in[5];
    const int* pos        = (const int*)d_in[7];
    float* out            = (float*)d_out;

    float *Q, *KV, *KPE, *KVB, *cosT, *sinT;
    __nv_bfloat16 *Xc, *KVCc, *ATTNc, *WqT, *WkvaT, *WkvbT, *WoT;
    __nv_bfloat16 *Qh, *Ql, *Kh, *Kl, *Vh, *Vl;
    cudaGetSymbolAddress((void**)&Q,     g_Q);
    cudaGetSymbolAddress((void**)&KV,    g_KV);
    cudaGetSymbolAddress((void**)&KPE,   g_KPE);
    cudaGetSymbolAddress((void**)&KVB,   g_KVB);
    cudaGetSymbolAddress((void**)&cosT,  g_COS);
    cudaGetSymbolAddress((void**)&sinT,  g_SIN);
    cudaGetSymbolAddress((void**)&Xc,    g_Xc);
    cudaGetSymbolAddress((void**)&KVCc,  g_KVCc);
    cudaGetSymbolAddress((void**)&ATTNc, g_ATTNc);
    cudaGetSymbolAddress((void**)&WqT,   g_WqT);
    cudaGetSymbolAddress((void**)&WkvaT, g_WkvaT);
    cudaGetSymbolAddress((void**)&WkvbT, g_WkvbT);
    cudaGetSymbolAddress((void**)&WoT,   g_WoT);
    cudaGetSymbolAddress((void**)&Qh,    g_Qh);
    cudaGetSymbolAddress((void**)&Ql,    g_Ql);
    cudaGetSymbolAddress((void**)&Kh,    g_Kh);
    cudaGetSymbolAddress((void**)&Kl,    g_Kl);
    cudaGetSymbolAddress((void**)&Vh,    g_Vh);
    cudaGetSymbolAddress((void**)&Vl,    g_Vl);

    cudaFuncSetAttribute(flash2_kernel,
                         cudaFuncAttributeMaxDynamicSharedMemorySize, FLASH2_SMEM);
    cudaFuncSetAttribute(mma_gemm,
                         cudaFuncAttributeMaxDynamicSharedMemorySize, GEMM_SMEM);

    dim3 blk(256);
    conv_cat_A<<<NROWS, blk>>>(x, Xc, 2048);
    convT_cat_B<<<dim3(4096 / 32, 2048 / 32), blk>>>(wq, WqT, 2048, 4096);
    convT_cat_B<<<dim3(640 / 32, 2048 / 32), blk>>>(wkv_a, WkvaT, 2048, 640);
    convT_cat_B<<<dim3(2048 / 32, 512 / 32), blk>>>(wkv_b, WkvbT, 512, 2048);
    convT_cat_B<<<dim3(2048 / 32, 2048 / 32), blk>>>(wo, WoT, 2048, 2048);
    rope_table_kernel<<<S_, 64>>>(pos, cosT, sinT);
    mma_gemm<<<dim3(32, 32), blk, GEMM_SMEM>>>(Xc, WqT, Q, 4096, 6144);       // q proj
    mma_gemm<<<dim3(6, 32), blk, GEMM_SMEM>>>(Xc, WkvaT, KV, 768, 6144);      // kv_a proj
    ln_rope_kernel<<<NROWS, blk>>>(KV, kv_scale, Q, KVCc, KPE, cosT, sinT);
    mma_gemm<<<dim3(16, 32), blk, GEMM_SMEM>>>(KVCc, WkvbT, KVB, 2048, 1536); // kv_b proj
    conv_q<<<NROWS, blk>>>(Q, Qh, Ql);
    conv_kvb<<<NROWS, blk>>>(KVB, KPE, Kh, Kl, Vh, Vl);
    flash2_kernel<<<dim3(32, H_, B_), blk, FLASH2_SMEM>>>(Qh, Ql, Kh, Kl, Vh, Vl, ATTNc);
    mma_gemm<<<dim3(16, 32), blk, GEMM_SMEM>>>(ATTNc, WoT, out, 2048, 6144);  // out proj
}

// round 8
// speedup vs baseline: 1.1829x; 1.0747x over previous
#include <cuda_runtime.h>
#include <cuda_bf16.h>
#include <cstdint>
#include <math.h>

#define B_    2
#define S_    2048
#define H_    16
#define NROWS 4096          // B_*S_

// ---------------- scratch (device globals: no allocs allowed) ----------------
__device__ float g_Q[NROWS * 4096];                  // q proj fp32 (pe cols only used)
__device__ float g_KV[NROWS * 768];                  // x @ wkv_a (padded 640->768)
__device__ float g_COS[S_ * 64];
__device__ float g_SIN[S_ * 64];
// bf16 split-cat buffers (GEMMs): A=[hi,lo,hi], B(transposed)=[hi,hi,lo]
__device__ __nv_bfloat16 g_Xc[NROWS * 6144];
__device__ __nv_bfloat16 g_KVCc[NROWS * 1536];
__device__ __nv_bfloat16 g_ATTNc[NROWS * 6144];
__device__ __nv_bfloat16 g_WqT[4096 * 6144];
__device__ __nv_bfloat16 g_WkvaT[768 * 6144];
__device__ __nv_bfloat16 g_WkvbT[2048 * 1536];
__device__ __nv_bfloat16 g_WoT[2048 * 6144];
// bf16 hi/lo planes for flash attention
__device__ __nv_bfloat16 g_Qh[NROWS * 4096];         // (b,s,h,256)
__device__ __nv_bfloat16 g_Ql[NROWS * 4096];
__device__ __nv_bfloat16 g_Kh[NROWS * 2048];         // (b,s,kvh,256) nope|pe
__device__ __nv_bfloat16 g_Kl[NROWS * 2048];
__device__ __nv_bfloat16 g_Vh[NROWS * 1024];         // (b,s,kvh,128)
__device__ __nv_bfloat16 g_Vl[NROWS * 1024];

// ================= helpers =================
__device__ __forceinline__ uint32_t smem_u32(const void* p) {
    uint32_t a;
    asm("{ .reg .u64 t; cvta.to.shared.u64 t, %1; cvt.u32.u64 %0, t; }" : "=r"(a) : "l"(p));
    return a;
}
__device__ __forceinline__ void cp_async16(uint32_t saddr, const void* gaddr) {
    asm volatile("cp.async.cg.shared.global [%0], [%1], 16;" :: "r"(saddr), "l"(gaddr));
}
__device__ __forceinline__ void cp_commit() { asm volatile("cp.async.commit_group;"); }
__device__ __forceinline__ void ldmatrix_x4(uint32_t& r0, uint32_t& r1, uint32_t& r2,
                                            uint32_t& r3, uint32_t addr) {
    asm volatile("ldmatrix.sync.aligned.m8n8.x4.shared.b16 {%0,%1,%2,%3}, [%4];"
                 : "=r"(r0), "=r"(r1), "=r"(r2), "=r"(r3) : "r"(addr));
}
__device__ __forceinline__ void ldmatrix_x4_t(uint32_t& r0, uint32_t& r1, uint32_t& r2,
                                              uint32_t& r3, uint32_t addr) {
    asm volatile("ldmatrix.sync.aligned.m8n8.x4.trans.shared.b16 {%0,%1,%2,%3}, [%4];"
                 : "=r"(r0), "=r"(r1), "=r"(r2), "=r"(r3) : "r"(addr));
}
__device__ __forceinline__ void mma16816(float* c, const uint32_t* a, const uint32_t* b) {
    asm volatile(
        "mma.sync.aligned.m16n8k16.row.col.f32.bf16.bf16.f32 "
        "{%0,%1,%2,%3}, {%4,%5,%6,%7}, {%8,%9}, {%0,%1,%2,%3};"
        : "+f"(c[0]), "+f"(c[1]), "+f"(c[2]), "+f"(c[3])
        : "r"(a[0]), "r"(a[1]), "r"(a[2]), "r"(a[3]), "r"(b[0]), "r"(b[1]));
}
__device__ __forceinline__ void split_bf16(float x, __nv_bfloat16& h, __nv_bfloat16& l) {
    h = __float2bfloat16(x);
    l = __float2bfloat16(x - __bfloat162float(h));
}

// ================= HMMA split-bf16 GEMM, 128x128, 4-stage, 2 CTAs/SM =================
// mode 0: C fp32.  mode 1 (q proj): nope cols -> Ph/Pl split, pe cols -> C fp32.
// mode 2 (kv_b): d<128 -> Ph/Pl (K nope), d>=128 -> Wh/Wl (V).
#define APAD 40
#define GSTG 4
#define STG_BYTES (128 * APAD * 2)            // 10240 per operand per stage
#define GEMM_SMEM (GSTG * STG_BYTES * 2)      // 81920

__global__ __launch_bounds__(256, 2) void mma_gemm(
    const __nv_bfloat16* __restrict__ A, const __nv_bfloat16* __restrict__ Bt,
    float* __restrict__ C, int N, int K3, int mode,
    __nv_bfloat16* __restrict__ Ph, __nv_bfloat16* __restrict__ Pl,
    __nv_bfloat16* __restrict__ Wh, __nv_bfloat16* __restrict__ Wl)
{
    extern __shared__ char gsm[];
    const uint32_t sA = smem_u32(gsm);
    const uint32_t sB = sA + GSTG * STG_BYTES;

    const int tid = threadIdx.x, wid = tid >> 5, lane = tid & 31;
    const int bm = blockIdx.y << 7, bn = blockIdx.x << 7;
    const int wm = (wid & 1) << 6;
    const int wn = (wid >> 1) << 5;
    const __nv_bfloat16* Ab = A + (size_t)bm * K3;
    const __nv_bfloat16* Bb = Bt + (size_t)bn * K3;
    const int nk = K3 >> 5;

    float acc[4][4][4];
#pragma unroll
    for (int i = 0; i < 4; i++)
#pragma unroll
        for (int j = 0; j < 4; j++)
#pragma unroll
            for (int k = 0; k < 4; k++) acc[i][j][k] = 0.f;

    const int r0 = tid >> 2, c0 = (tid & 3) << 3;
    const int r1 = (tid + 256) >> 2;

#define LOAD_STAGE(kt, s) do {                                                        \
    size_t kb = (size_t)(kt) << 5;                                                    \
    cp_async16(sA + (s) * STG_BYTES + (r0 * APAD + c0) * 2,                           \
               Ab + (size_t)r0 * K3 + kb + c0);                                       \
    cp_async16(sA + (s) * STG_BYTES + (r1 * APAD + c0) * 2,                           \
               Ab + (size_t)r1 * K3 + kb + c0);                                       \
    cp_async16(sB + (s) * STG_BYTES + (r0 * APAD + c0) * 2,                           \
               Bb + (size_t)r0 * K3 + kb + c0);                                       \
    cp_async16(sB + (s) * STG_BYTES + (r1 * APAD + c0) * 2,                           \
               Bb + (size_t)r1 * K3 + kb + c0);                                       \
} while (0)

    LOAD_STAGE(0, 0); cp_commit();
    LOAD_STAGE(1, 1); cp_commit();
    LOAD_STAGE(2, 2); cp_commit();

    const int a_row = wm + (lane & 15);
    const int a_col = (lane >> 4) << 3;
    const int b_row = ((lane >> 4) & 1) * 8 + (lane & 7);
    const int b_col = ((lane >> 3) & 1) << 3;

    for (int kt = 0; kt < nk; kt++) {
        asm volatile("cp.async.wait_group 2;");
        __syncthreads();
        if (kt + 3 < nk) LOAD_STAGE(kt + 3, (kt + 3) & (GSTG - 1));
        cp_commit();

        const int s = kt & (GSTG - 1);
        const uint32_t aBase = sA + s * STG_BYTES;
        const uint32_t bBase = sB + s * STG_BYTES;
#pragma unroll
        for (int ks = 0; ks < 2; ks++) {
            uint32_t a[4][4], b[2][4];
#pragma unroll
            for (int mi = 0; mi < 4; mi++)
                ldmatrix_x4(a[mi][0], a[mi][1], a[mi][2], a[mi][3],
                            aBase + 2 * ((a_row + mi * 16) * APAD + ks * 16 + a_col));
#pragma unroll
            for (int nj = 0; nj < 2; nj++)
                ldmatrix_x4(b[nj][0], b[nj][1], b[nj][2], b[nj][3],
                            bBase + 2 * ((wn + nj * 16 + b_row) * APAD + ks * 16 + b_col));
#pragma unroll
            for (int mi = 0; mi < 4; mi++)
#pragma unroll
                for (int nt = 0; nt < 4; nt++)
                    mma16816(acc[mi][nt], a[mi], &b[nt >> 1][(nt & 1) * 2]);
        }
    }

    const int g = lane >> 2, tl = lane & 3;
#pragma unroll
    for (int mi = 0; mi < 4; mi++) {
#pragma unroll
        for (int nt = 0; nt < 4; nt++) {
#pragma unroll
            for (int half = 0; half < 2; half++) {
                int row = bm + wm + mi * 16 + g + half * 8;
                int col = bn + wn + nt * 8 + tl * 2;
                float v0 = acc[mi][nt][half * 2 + 0];
                float v1 = acc[mi][nt][half * 2 + 1];
                if (mode == 0) {
                    *(float2*)(C + (size_t)row * N + col) = make_float2(v0, v1);
                } else if (mode == 1) {
                    int d = col & 255;
                    if (d < 128) {
                        __nv_bfloat16 h0, l0, h1, l1;
                        split_bf16(v0, h0, l0); split_bf16(v1, h1, l1);
                        *(__nv_bfloat162*)(Ph + (size_t)row * 4096 + col) = __nv_bfloat162(h0, h1);
                        *(__nv_bfloat162*)(Pl + (size_t)row * 4096 + col) = __nv_bfloat162(l0, l1);
                    } else {
                        *(float2*)(C + (size_t)row * N + col) = make_float2(v0, v1);
                    }
                } else {
                    int d = col & 255;
                    __nv_bfloat16 h0, l0, h1, l1;
                    split_bf16(v0, h0, l0); split_bf16(v1, h1, l1);
                    if (d < 128) {
                        *(__nv_bfloat162*)(Ph + (size_t)row * 2048 + col) = __nv_bfloat162(h0, h1);
                        *(__nv_bfloat162*)(Pl + (size_t)row * 2048 + col) = __nv_bfloat162(l0, l1);
                    } else {
                        int kvh = col >> 8;
                        size_t vi = (size_t)row * 1024 + kvh * 128 + (d - 128);
                        *(__nv_bfloat162*)(Wh + vi) = __nv_bfloat162(h0, h1);
                        *(__nv_bfloat162*)(Wl + vi) = __nv_bfloat162(l0, l1);
                    }
                }
            }
        }
    }
#undef LOAD_STAGE
}

// ================= conversion kernels =================
__global__ __launch_bounds__(256) void conv_cat_A(
    const float* __restrict__ X, __nv_bfloat16* __restrict__ Y, int K)
{
    const int row = blockIdx.x;
    const float* xr = X + (size_t)row * K;
    __nv_bfloat16* yr = Y + (size_t)row * 3 * K;
    for (int c = threadIdx.x; c < K; c += 256) {
        __nv_bfloat16 h, l;
        split_bf16(xr[c], h, l);
        yr[c] = h; yr[K + c] = l; yr[2 * K + c] = h;
    }
}
__global__ __launch_bounds__(256) void convT_cat_B(
    const float* __restrict__ W, __nv_bfloat16* __restrict__ Y, int K, int N)
{
    __shared__ float s[32][33];
    const int tx = threadIdx.x & 31, ty = threadIdx.x >> 5;
    const int n0 = blockIdx.x << 5, k0 = blockIdx.y << 5;
#pragma unroll
    for (int i = 0; i < 4; i++)
        s[ty + 8 * i][tx] = W[(size_t)(k0 + ty + 8 * i) * N + n0 + tx];
    __syncthreads();
#pragma unroll
    for (int i = 0; i < 4; i++) {
        int n = n0 + ty + 8 * i, k = k0 + tx;
        __nv_bfloat16 h, l;
        split_bf16(s[tx][ty + 8 * i], h, l);
        __nv_bfloat16* yr = Y + (size_t)n * 3 * K;
        yr[k] = h; yr[K + k] = h; yr[2 * K + k] = l;
    }
}

// ---------------- rope cos/sin table ----------------
__global__ void rope_table_kernel(const int* __restrict__ pos,
                                  float* __restrict__ cosT, float* __restrict__ sinT)
{
    int s = blockIdx.x, i = threadIdx.x;
    double e = (double)i / 64.0;
    float t = (float)pow(10000.0, e);
    float freq = (1.0f / t) * 40.0f;
    float ang = (float)pos[s] * freq;
    cosT[s * 64 + i] = (float)cos((double)ang);
    sinT[s * 64 + i] = (float)sin((double)ang);
}

// ---------------- layernorm + rope (writes splits directly) ----------------
__global__ __launch_bounds__(256) void ln_rope_kernel(
    const float* __restrict__ KV, const float* __restrict__ lnscale,
    const float* __restrict__ Qf, __nv_bfloat16* __restrict__ KVCc,
    __nv_bfloat16* __restrict__ Qh, __nv_bfloat16* __restrict__ Ql,
    __nv_bfloat16* __restrict__ Kh, __nv_bfloat16* __restrict__ Kl,
    const float* __restrict__ cosT, const float* __restrict__ sinT)
{
    const int row = blockIdx.x;
    const int tid = threadIdx.x;
    const int s = row & (S_ - 1);
    const float* kvr = KV + (size_t)row * 768;

    float v0 = kvr[tid], v1 = kvr[tid + 256];
    float sum = v0 + v1, sq = v0 * v0 + v1 * v1;
#pragma unroll
    for (int o = 16; o > 0; o >>= 1) {
        sum += __shfl_xor_sync(0xffffffffu, sum, o);
        sq  += __shfl_xor_sync(0xffffffffu, sq, o);
    }
    __shared__ float red[16];
    if ((tid & 31) == 0) { red[tid >> 5] = sum; red[(tid >> 5) + 8] = sq; }
    __syncthreads();
    float tot = 0.f, tot2 = 0.f;
#pragma unroll
    for (int i = 0; i < 8; i++) { tot += red[i]; tot2 += red[i + 8]; }
    float mean = tot * (1.f / 512.f);
    float var  = tot2 * (1.f / 512.f) - mean * mean;
    float inv  = rsqrtf(var + 1e-5f);
    float y0 = (v0 - mean) * inv * lnscale[tid];
    float y1 = (v1 - mean) * inv * lnscale[tid + 256];
    {
        __nv_bfloat16 h, l;
        __nv_bfloat16* yr = KVCc + (size_t)row * 1536;
        split_bf16(y0, h, l);
        yr[tid] = h; yr[512 + tid] = l; yr[1024 + tid] = h;
        split_bf16(y1, h, l);
        yr[tid + 256] = h; yr[512 + tid + 256] = l; yr[1024 + tid + 256] = h;
    }

    // k_pe rope + split, broadcast to all 8 kvh slots
    if (tid < 64) {
        float c = cosT[s * 64 + tid], sn = sinT[s * 64 + tid];
        float xr = kvr[512 + 2 * tid], xi = kvr[512 + 2 * tid + 1];
        float p0 = xr * c - xi * sn;
        float p1 = xr * sn + xi * c;
        __nv_bfloat16 h0, l0, h1, l1;
        split_bf16(p0, h0, l0); split_bf16(p1, h1, l1);
        __nv_bfloat162 hv(h0, h1), lv(l0, l1);
#pragma unroll
        for (int kvh = 0; kvh < 8; kvh++) {
            size_t ki = (size_t)row * 2048 + kvh * 256 + 128 + 2 * tid;
            *(__nv_bfloat162*)(Kh + ki) = hv;
            *(__nv_bfloat162*)(Kl + ki) = lv;
        }
    }
    // q_pe rope + split
#pragma unroll
    for (int t = tid; t < 1024; t += 256) {
        int hh = t >> 6, i = t & 63;
        float c = cosT[s * 64 + i], sn = sinT[s * 64 + i];
        const float* qp = Qf + (size_t)row * 4096 + hh * 256 + 128 + 2 * i;
        float xr = qp[0], xi = qp[1];
        float p0 = xr * c - xi * sn;
        float p1 = xr * sn + xi * c;
        __nv_bfloat16 h0, l0, h1, l1;
        split_bf16(p0, h0, l0); split_bf16(p1, h1, l1);
        size_t qi_ = (size_t)row * 4096 + hh * 256 + 128 + 2 * i;
        *(__nv_bfloat162*)(Qh + qi_) = __nv_bfloat162(h0, h1);
        *(__nv_bfloat162*)(Ql + qi_) = __nv_bfloat162(l0, l1);
    }
}

// ================= flash attention: HMMA, split-bf16, pipelined, merged passes =================
#define FQ_H   0
#define FQ_L   16896
#define FK_H   33792
#define FK_L   50688
#define FV_H   67584          // [64][136]
#define FV_L   76288
#define FP_H   84992          // [64][72]
#define FP_L   89600
#define FS_B   188416         // S [64][68] fp32 (byte offset)
#define FA_B   205824
#define FL_B   206080
#define FLASH2_SMEM 206336

__global__ __launch_bounds__(256) void flash2_kernel(
    const __nv_bfloat16* __restrict__ Qh, const __nv_bfloat16* __restrict__ Ql,
    const __nv_bfloat16* __restrict__ Kh, const __nv_bfloat16* __restrict__ Kl,
    const __nv_bfloat16* __restrict__ Vh, const __nv_bfloat16* __restrict__ Vl,
    __nv_bfloat16* __restrict__ ATTNc)
{
    extern __shared__ __nv_bfloat16 sm[];
    const uint32_t sb = smem_u32(sm);
    float* Ssm  = (float*)((char*)sm + FS_B);
    float* Asm  = (float*)((char*)sm + FA_B);
    float* Lsm  = (float*)((char*)sm + FL_B);

    const int tid = threadIdx.x, wid = tid >> 5, lane = tid & 31;
    const int qi = 31 - blockIdx.x;       // heavy tiles first
    const int hh = blockIdx.y, b = blockIdx.z;
    const int kvh = hh >> 1;
    const int qb = b * S_ + qi * 64;

#define LOAD_K(kb_) do {                                                        \
    for (int idx = tid; idx < 2048; idx += 256) {                               \
        int row = idx >> 5, c8 = (idx & 31) << 3;                               \
        const size_t gk = (size_t)((kb_) + row) * 2048 + kvh * 256 + c8;        \
        cp_async16(sb + (FK_H + row * 264 + c8) * 2, Kh + gk);                  \
        cp_async16(sb + (FK_L + row * 264 + c8) * 2, Kl + gk);                  \
    } } while (0)
#define LOAD_V(kb_) do {                                                        \
    for (int idx = tid; idx < 1024; idx += 256) {                               \
        int row = idx >> 4, c8 = (idx & 15) << 3;                               \
        const size_t gv = (size_t)((kb_) + row) * 1024 + kvh * 128 + c8;        \
        cp_async16(sb + (FV_H + row * 136 + c8) * 2, Vh + gv);                  \
        cp_async16(sb + (FV_L + row * 136 + c8) * 2, Vl + gv);                  \
    } } while (0)

    // prologue: K(0), Q, V(0)
    LOAD_K(b * S_); cp_commit();
    for (int idx = tid; idx < 2048; idx += 256) {
        int row = idx >> 5, c8 = (idx & 31) << 3;
        const size_t g = (size_t)(qb + row) * 4096 + hh * 256 + c8;
        cp_async16(sb + (FQ_H + row * 264 + c8) * 2, Qh + g);
        cp_async16(sb + (FQ_L + row * 264 + c8) * 2, Ql + g);
    }
    cp_commit();
    LOAD_V(b * S_); cp_commit();
    asm volatile("cp.async.wait_group 1;");
    __syncthreads();

    const int srow = wid * 8 + (lane >> 2);
    const int stl = lane & 3;
    float m = -INFINITY, lacc = 0.f;

    const int wmS = (wid & 3) << 4, wnS = (wid >> 2) << 5;
    const int vm = (wid & 3) << 4, vn = (wid >> 2) << 6;

    const int a_row = lane & 15, a_colo = (lane >> 4) << 3;
    const int b_row = ((lane >> 4) & 1) * 8 + (lane & 7);
    const int b_col = ((lane >> 3) & 1) << 3;
    const int g = lane >> 2, tl = lane & 3;

    float oacc[8][4];
#pragma unroll
    for (int i = 0; i < 8; i++)
#pragma unroll
        for (int j = 0; j < 4; j++) oacc[i][j] = 0.f;

    const float scale = 0.08838834764831845f;

    for (int kt = 0; kt <= qi; kt++) {
        const bool has_next = (kt < qi);
        const int kb_next = b * S_ + (kt + 1) * 64;

        // ---- S = Q K^T, merged 3-combo split (hh + lh + hl) ----
        float sacc[4][4];
#pragma unroll
        for (int i = 0; i < 4; i++)
#pragma unroll
            for (int j = 0; j < 4; j++) sacc[i][j] = 0.f;
#pragma unroll
        for (int kc = 0; kc < 16; kc++) {
            uint32_t qh[4], ql[4], kh[2][4], kl[2][4];
            ldmatrix_x4(qh[0], qh[1], qh[2], qh[3],
                        sb + FQ_H * 2 + 2 * ((wmS + a_row) * 264 + kc * 16 + a_colo));
            ldmatrix_x4(ql[0], ql[1], ql[2], ql[3],
                        sb + FQ_L * 2 + 2 * ((wmS + a_row) * 264 + kc * 16 + a_colo));
#pragma unroll
            for (int nj = 0; nj < 2; nj++) {
                ldmatrix_x4(kh[nj][0], kh[nj][1], kh[nj][2], kh[nj][3],
                            sb + FK_H * 2 + 2 * ((wnS + nj * 16 + b_row) * 264 + kc * 16 + b_col));
                ldmatrix_x4(kl[nj][0], kl[nj][1], kl[nj][2], kl[nj][3],
                            sb + FK_L * 2 + 2 * ((wnS + nj * 16 + b_row) * 264 + kc * 16 + b_col));
            }
#pragma unroll
            for (int nt = 0; nt < 4; nt++) {
                mma16816(sacc[nt], qh, &kh[nt >> 1][(nt & 1) * 2]);
                mma16816(sacc[nt], ql, &kh[nt >> 1][(nt & 1) * 2]);
                mma16816(sacc[nt], qh, &kl[nt >> 1][(nt & 1) * 2]);
            }
        }
#pragma unroll
        for (int nt = 0; nt < 4; nt++) {
            int col = wnS + nt * 8 + tl * 2;
            *(float2*)(Ssm + (wmS + g) * 68 + col) = make_float2(sacc[nt][0], sacc[nt][1]);
            *(float2*)(Ssm + (wmS + g + 8) * 68 + col) = make_float2(sacc[nt][2], sacc[nt][3]);
        }
        __syncthreads();                       // K smem free, S staged

        // ---- prefetch K(kt+1) ----
        if (has_next) { LOAD_K(kb_next); }
        cp_commit();

        // ---- softmax (fp32), P split to bf16 hi/lo ----
        {
            float sv[16];
            const bool diag = (kt == qi);
#pragma unroll
            for (int j = 0; j < 16; j++) {
                int c = stl + 4 * j;
                float v = Ssm[srow * 68 + c] * scale;
                if (diag && c > srow) v = -INFINITY;
                sv[j] = v;
            }
            float mt = sv[0];
#pragma unroll
            for (int j = 1; j < 16; j++) mt = fmaxf(mt, sv[j]);
            mt = fmaxf(mt, __shfl_xor_sync(0xffffffffu, mt, 1));
            mt = fmaxf(mt, __shfl_xor_sync(0xffffffffu, mt, 2));
            float mnew = fmaxf(m, mt);
            float alpha = __expf(m - mnew);
            float rs = 0.f;
            __nv_bfloat16* PhS = sm + FP_H + srow * 72;
            __nv_bfloat16* PlS = sm + FP_L + srow * 72;
#pragma unroll
            for (int j = 0; j < 16; j++) {
                float p = __expf(sv[j] - mnew);
                rs += p;
                __nv_bfloat16 hb, lb;
                split_bf16(p, hb, lb);
                int c = stl + 4 * j;
                PhS[c] = hb; PlS[c] = lb;
            }
            rs += __shfl_xor_sync(0xffffffffu, rs, 1);
            rs += __shfl_xor_sync(0xffffffffu, rs, 2);
            lacc = lacc * alpha + rs;
            m = mnew;
            if (stl == 0) Asm[srow] = alpha;
        }
        __syncthreads();                       // P, alpha visible

        // ---- wait V(kt) ----
        asm volatile("cp.async.wait_group 1;");
        __syncthreads();

        // ---- O = O*alpha + P V, merged 3-combo split ----
        {
            float ag = Asm[vm + g], ag8 = Asm[vm + g + 8];
#pragma unroll
            for (int nt = 0; nt < 8; nt++) {
                oacc[nt][0] *= ag;  oacc[nt][1] *= ag;
                oacc[nt][2] *= ag8; oacc[nt][3] *= ag8;
            }
#pragma unroll
            for (int kc = 0; kc < 4; kc++) {
                uint32_t ph[4], pl[4], vhf[4][4], vlf[4][4];
                ldmatrix_x4(ph[0], ph[1], ph[2], ph[3],
                            sb + FP_H * 2 + 2 * ((vm + a_row) * 72 + kc * 16 + a_colo));
                ldmatrix_x4(pl[0], pl[1], pl[2], pl[3],
                            sb + FP_L * 2 + 2 * ((vm + a_row) * 72 + kc * 16 + a_colo));
#pragma unroll
                for (int nj = 0; nj < 4; nj++) {
                    ldmatrix_x4_t(vhf[nj][0], vhf[nj][1], vhf[nj][2], vhf[nj][3],
                                  sb + FV_H * 2 + 2 * ((kc * 16 + (lane & 15)) * 136 +
                                                       vn + nj * 16 + a_colo));
                    ldmatrix_x4_t(vlf[nj][0], vlf[nj][1], vlf[nj][2], vlf[nj][3],
                                  sb + FV_L * 2 + 2 * ((kc * 16 + (lane & 15)) * 136 +
                                                       vn + nj * 16 + a_colo));
                }
#pragma unroll
                for (int nt = 0; nt < 8; nt++) {
                    mma16816(oacc[nt], ph, &vhf[nt >> 1][(nt & 1) * 2]);
                    mma16816(oacc[nt], pl, &vhf[nt >> 1][(nt & 1) * 2]);
                    mma16816(oacc[nt], ph, &vlf[nt >> 1][(nt & 1) * 2]);
                }
            }
        }
        __syncthreads();                       // V, P free

        // ---- prefetch V(kt+1); wait K(kt+1) ----
        if (has_next) {
            LOAD_V(kb_next); cp_commit();
            asm volatile("cp.async.wait_group 1;");
            __syncthreads();
        }
    }

    // ---- epilogue ----
    if (stl == 0) Lsm[srow] = 1.f / lacc;
    __syncthreads();
    {
        float lg = Lsm[vm + g], lg8 = Lsm[vm + g + 8];
#pragma unroll
        for (int nt = 0; nt < 8; nt++) {
            int col = vn + nt * 8 + tl * 2;
            float v0 = oacc[nt][0] * lg,  v1 = oacc[nt][1] * lg;
            float v2 = oacc[nt][2] * lg8, v3 = oacc[nt][3] * lg8;
            __nv_bfloat16 h0, l0, h1, l1;
            __nv_bfloat16* base0 = ATTNc + (size_t)(qb + vm + g) * 6144 + hh * 128;
            split_bf16(v0, h0, l0); split_bf16(v1, h1, l1);
            *(__nv_bfloat162*)(base0 + col)        = __nv_bfloat162(h0, h1);
            *(__nv_bfloat162*)(base0 + 2048 + col) = __nv_bfloat162(l0, l1);
            *(__nv_bfloat162*)(base0 + 4096 + col) = __nv_bfloat162(h0, h1);
            __nv_bfloat16* base1 = ATTNc + (size_t)(qb + vm + g + 8) * 6144 + hh * 128;
            split_bf16(v2, h0, l0); split_bf16(v3, h1, l1);
            *(__nv_bfloat162*)(base1 + col)        = __nv_bfloat162(h0, h1);
            *(__nv_bfloat162*)(base1 + 2048 + col) = __nv_bfloat162(l0, l1);
            *(__nv_bfloat162*)(base1 + 4096 + col) = __nv_bfloat162(h0, h1);
        }
    }
#undef LOAD_K
#undef LOAD_V
}

// ---------------- launcher ----------------
extern "C" void kernel_launch(void* const* d_in, const int* in_sizes, int n_in,
                              void* d_out, int out_size)
{
    const float* x        = (const float*)d_in[0];
    const float* wq       = (const float*)d_in[1];
    const float* wkv_a    = (const float*)d_in[2];
    const float* kv_scale = (const float*)d_in[3];
    const float* wkv_b    = (const float*)d_in[4];
    const float* wo       = (const float*)d_in[5];
    const int* pos        = (const int*)d_in[7];
    float* out            = (float*)d_out;

    float *Q, *KV, *cosT, *sinT;
    __nv_bfloat16 *Xc, *KVCc, *ATTNc, *WqT, *WkvaT, *WkvbT, *WoT;
    __nv_bfloat16 *Qh, *Ql, *Kh, *Kl, *Vh, *Vl;
    cudaGetSymbolAddress((void**)&Q,     g_Q);
    cudaGetSymbolAddress((void**)&KV,    g_KV);
    cudaGetSymbolAddress((void**)&cosT,  g_COS);
    cudaGetSymbolAddress((void**)&sinT,  g_SIN);
    cudaGetSymbolAddress((void**)&Xc,    g_Xc);
    cudaGetSymbolAddress((void**)&KVCc,  g_KVCc);
    cudaGetSymbolAddress((void**)&ATTNc, g_ATTNc);
    cudaGetSymbolAddress((void**)&WqT,   g_WqT);
    cudaGetSymbolAddress((void**)&WkvaT, g_WkvaT);
    cudaGetSymbolAddress((void**)&WkvbT, g_WkvbT);
    cudaGetSymbolAddress((void**)&WoT,   g_WoT);
    cudaGetSymbolAddress((void**)&Qh,    g_Qh);
    cudaGetSymbolAddress((void**)&Ql,    g_Ql);
    cudaGetSymbolAddress((void**)&Kh,    g_Kh);
    cudaGetSymbolAddress((void**)&Kl,    g_Kl);
    cudaGetSymbolAddress((void**)&Vh,    g_Vh);
    cudaGetSymbolAddress((void**)&Vl,    g_Vl);

    cudaFuncSetAttribute(flash2_kernel,
                         cudaFuncAttributeMaxDynamicSharedMemorySize, FLASH2_SMEM);
    cudaFuncSetAttribute(mma_gemm,
                         cudaFuncAttributeMaxDynamicSharedMemorySize, GEMM_SMEM);

    dim3 blk(256);
    conv_cat_A<<<NROWS, blk>>>(x, Xc, 2048);
    convT_cat_B<<<dim3(4096 / 32, 2048 / 32), blk>>>(wq, WqT, 2048, 4096);
    convT_cat_B<<<dim3(640 / 32, 2048 / 32), blk>>>(wkv_a, WkvaT, 2048, 640);
    convT_cat_B<<<dim3(2048 / 32, 512 / 32), blk>>>(wkv_b, WkvbT, 512, 2048);
    convT_cat_B<<<dim3(2048 / 32, 2048 / 32), blk>>>(wo, WoT, 2048, 2048);
    rope_table_kernel<<<S_, 64>>>(pos, cosT, sinT);
    // q proj: nope -> Qh/Ql split, pe -> Q fp32
    mma_gemm<<<dim3(32, 32), blk, GEMM_SMEM>>>(Xc, WqT, Q, 4096, 6144, 1, Qh, Ql, nullptr, nullptr);
    // kv_a proj: plain fp32
    mma_gemm<<<dim3(6, 32), blk, GEMM_SMEM>>>(Xc, WkvaT, KV, 768, 6144, 0, nullptr, nullptr, nullptr, nullptr);
    ln_rope_kernel<<<NROWS, blk>>>(KV, kv_scale, Q, KVCc, Qh, Ql, Kh, Kl, cosT, sinT);
    // kv_b proj: K nope -> Kh/Kl, V -> Vh/Vl
    mma_gemm<<<dim3(16, 32), blk, GEMM_SMEM>>>(KVCc, WkvbT, nullptr, 2048, 1536, 2, Kh, Kl, Vh, Vl);
    flash2_kernel<<<dim3(32, H_, B_), blk, FLASH2_SMEM>>>(Qh, Ql, Kh, Kl, Vh, Vl, ATTNc);
    // out proj: plain fp32 to harness output
    mma_gemm<<<dim3(16, 32), blk, GEMM_SMEM>>>(ATTNc, WoT, out, 2048, 6144, 0, nullptr, nullptr, nullptr, nullptr);
}